// round 1
// baseline (speedup 1.0000x reference)
#include <cuda_runtime.h>
#include <math.h>

// ---------------------------------------------------------------------------
// AttentiveBimodalCSRPool — fp32 baseline with packed f32x2 FMA GEMMs.
//
// Pipeline:
//   seg[v]   : CSR expansion
//   Q        : x_main @ Wq + bq                       [N,64]
//   Y1       : x_proj @ W1 + b1 (+batch stats)        [V,64]
//   bn1      : finalize scale/shift
//   Y2       : relu(bn1(Y1)) @ W2 + b2 (+stats)       [V,64]
//   bn2      : finalize
//   X        : dot( relu(bn2(Y2))@WkA + x_mod@WkB + bk , Q[seg] )   [V]
//   pool     : per-segment scaled softmax + weighted max-pool + gate
// ---------------------------------------------------------------------------

#define MAXV 1000000
#define MAXN 125056

__device__ float g_Q[(size_t)MAXN * 64];
__device__ float g_Y1[(size_t)MAXV * 64];
__device__ float g_Y2[(size_t)MAXV * 64];
__device__ float g_X[MAXV];
__device__ int   g_seg[MAXV];
__device__ float g_stats[256];   // [sum1(64), sq1(64), sum2(64), sq2(64)]
__device__ float g_bn1[128];     // [scale(64), shift(64)]
__device__ float g_bn2[128];

// ---- packed f32x2 helpers (sm_103a FFMA2 path) ----------------------------
__device__ __forceinline__ unsigned long long pk2(float lo, float hi) {
    unsigned long long r;
    asm("mov.b64 %0, {%1, %2};" : "=l"(r) : "f"(lo), "f"(hi));
    return r;
}
__device__ __forceinline__ unsigned long long fma2(unsigned long long a,
                                                   unsigned long long b,
                                                   unsigned long long c) {
    unsigned long long d;
    asm("fma.rn.f32x2 %0, %1, %2, %3;" : "=l"(d) : "l"(a), "l"(b), "l"(c));
    return d;
}
__device__ __forceinline__ void upk2(unsigned long long v, float& lo, float& hi) {
    asm("mov.b64 {%0, %1}, %2;" : "=f"(lo), "=f"(hi) : "l"(v));
}

// ---- 64-row x 64-col tile micro-kernel ------------------------------------
// 256 threads: tx = tid&15 owns 4 cols (c0=tx*4), ty = tid>>4 owns rows ty+16*i.
template <int KDIM>
__device__ __forceinline__ void mm_tile(const float* __restrict__ sIn,  // [64][KDIM]
                                        const float* __restrict__ sW,   // [KDIM][64]
                                        unsigned long long acc[4][2],
                                        int tx, int ty) {
    const int c0 = tx * 4;
#pragma unroll
    for (int k = 0; k < KDIM; ++k) {
        float4 w = *reinterpret_cast<const float4*>(&sW[k * 64 + c0]);
        unsigned long long w0 = pk2(w.x, w.y);
        unsigned long long w1 = pk2(w.z, w.w);
#pragma unroll
        for (int i = 0; i < 4; ++i) {
            float a = sIn[(ty + 16 * i) * KDIM + k];
            unsigned long long ap = pk2(a, a);
            acc[i][0] = fma2(ap, w0, acc[i][0]);
            acc[i][1] = fma2(ap, w1, acc[i][1]);
        }
    }
}

// ---------------------------------------------------------------------------
__global__ void k_zero_stats() {
    if (threadIdx.x < 256) g_stats[threadIdx.x] = 0.f;
}

__global__ void k_seg(const int* __restrict__ csr, int N) {
    int n = blockIdx.x * blockDim.x + threadIdx.x;
    if (n < N) {
        int s = csr[n], e = csr[n + 1];
        for (int v = s; v < e; ++v) g_seg[v] = n;
    }
}

// ---- Q = x_main @ Wq + bq  -------------------------------------------------
__global__ __launch_bounds__(256) void k_qgemm(const float* __restrict__ xin,
                                               const float* __restrict__ W,
                                               const float* __restrict__ b, int N) {
    __shared__ __align__(16) float sW[64 * 64];
    __shared__ __align__(16) float sIn[64 * 64];
    int tid = threadIdx.x;
    int row0 = blockIdx.x * 64;
    for (int i = tid; i < 64 * 64; i += 256) sW[i] = W[i];
    for (int i = tid; i < 64 * 64; i += 256) {
        int r = i >> 6, c = i & 63;
        int row = row0 + r;
        sIn[i] = (row < N) ? xin[(size_t)row * 64 + c] : 0.f;
    }
    __syncthreads();
    int tx = tid & 15, ty = tid >> 4;
    unsigned long long acc[4][2] = {};
    mm_tile<64>(sIn, sW, acc, tx, ty);
    int c0 = tx * 4;
    float b0 = b[c0], b1 = b[c0 + 1], b2 = b[c0 + 2], b3 = b[c0 + 3];
#pragma unroll
    for (int i = 0; i < 4; ++i) {
        int row = row0 + ty + 16 * i;
        if (row < N) {
            float y0, y1, y2, y3;
            upk2(acc[i][0], y0, y1);
            upk2(acc[i][1], y2, y3);
            float4 o = make_float4(y0 + b0, y1 + b1, y2 + b2, y3 + b3);
            *reinterpret_cast<float4*>(&g_Q[(size_t)row * 64 + c0]) = o;
        }
    }
}

// ---- Y1 = x_proj @ W1 + b1, accumulate batch stats ------------------------
__global__ __launch_bounds__(256) void k_gemm1(const float* __restrict__ xproj,
                                               const float* __restrict__ W,
                                               const float* __restrict__ b, int V) {
    __shared__ __align__(16) float sW[32 * 64];
    __shared__ __align__(16) float sIn[64 * 32];
    __shared__ float sSum[64], sSq[64];
    int tid = threadIdx.x;
    int row0 = blockIdx.x * 64;
    for (int i = tid; i < 32 * 64; i += 256) sW[i] = W[i];
    if (tid < 64) { sSum[tid] = 0.f; sSq[tid] = 0.f; }
    for (int i = tid; i < 64 * 32; i += 256) {
        int r = i >> 5, c = i & 31;
        int row = row0 + r;
        sIn[i] = (row < V) ? xproj[(size_t)row * 32 + c] : 0.f;
    }
    __syncthreads();
    int tx = tid & 15, ty = tid >> 4;
    unsigned long long acc[4][2] = {};
    mm_tile<32>(sIn, sW, acc, tx, ty);
    int c0 = tx * 4;
    float bb0 = b[c0], bb1 = b[c0 + 1], bb2 = b[c0 + 2], bb3 = b[c0 + 3];
    float s0 = 0, s1 = 0, s2 = 0, s3 = 0, q0 = 0, q1 = 0, q2 = 0, q3 = 0;
#pragma unroll
    for (int i = 0; i < 4; ++i) {
        int row = row0 + ty + 16 * i;
        if (row < V) {
            float y0, y1, y2, y3;
            upk2(acc[i][0], y0, y1);
            upk2(acc[i][1], y2, y3);
            y0 += bb0; y1 += bb1; y2 += bb2; y3 += bb3;
            *reinterpret_cast<float4*>(&g_Y1[(size_t)row * 64 + c0]) =
                make_float4(y0, y1, y2, y3);
            s0 += y0; s1 += y1; s2 += y2; s3 += y3;
            q0 += y0 * y0; q1 += y1 * y1; q2 += y2 * y2; q3 += y3 * y3;
        }
    }
    atomicAdd(&sSum[c0], s0);     atomicAdd(&sSq[c0], q0);
    atomicAdd(&sSum[c0 + 1], s1); atomicAdd(&sSq[c0 + 1], q1);
    atomicAdd(&sSum[c0 + 2], s2); atomicAdd(&sSq[c0 + 2], q2);
    atomicAdd(&sSum[c0 + 3], s3); atomicAdd(&sSq[c0 + 3], q3);
    __syncthreads();
    if (tid < 64) {
        atomicAdd(&g_stats[tid], sSum[tid]);
        atomicAdd(&g_stats[64 + tid], sSq[tid]);
    }
}

// ---- finalize BN params: scale = g/sqrt(var+eps), shift = beta - mean*scale
__global__ void k_finalize(const float* __restrict__ gg,
                           const float* __restrict__ bb, int stage, float invV) {
    int c = threadIdx.x;
    if (c >= 64) return;
    float* bn = stage ? g_bn2 : g_bn1;
    int off = stage ? 128 : 0;
    float mean = g_stats[off + c] * invV;
    float var  = g_stats[off + 64 + c] * invV - mean * mean;
    float sc = gg[c] / sqrtf(var + 1e-5f);
    bn[c] = sc;
    bn[64 + c] = bb[c] - mean * sc;
}

// ---- Y2 = relu(bn1(Y1)) @ W2 + b2, accumulate stats -----------------------
__global__ __launch_bounds__(256) void k_gemm2(const float* __restrict__ W,
                                               const float* __restrict__ b, int V) {
    __shared__ __align__(16) float sW[64 * 64];
    __shared__ __align__(16) float sIn[64 * 64];
    __shared__ float sSum[64], sSq[64];
    int tid = threadIdx.x;
    int row0 = blockIdx.x * 64;
    for (int i = tid; i < 64 * 64; i += 256) sW[i] = W[i];
    if (tid < 64) { sSum[tid] = 0.f; sSq[tid] = 0.f; }
    for (int i = tid; i < 64 * 64; i += 256) {
        int r = i >> 6, c = i & 63;
        int row = row0 + r;
        float y = (row < V) ? g_Y1[(size_t)row * 64 + c] : 0.f;
        sIn[i] = fmaxf(fmaf(y, __ldg(&g_bn1[c]), __ldg(&g_bn1[64 + c])), 0.f);
    }
    __syncthreads();
    int tx = tid & 15, ty = tid >> 4;
    unsigned long long acc[4][2] = {};
    mm_tile<64>(sIn, sW, acc, tx, ty);
    int c0 = tx * 4;
    float bb0 = b[c0], bb1 = b[c0 + 1], bb2 = b[c0 + 2], bb3 = b[c0 + 3];
    float s0 = 0, s1 = 0, s2 = 0, s3 = 0, q0 = 0, q1 = 0, q2 = 0, q3 = 0;
#pragma unroll
    for (int i = 0; i < 4; ++i) {
        int row = row0 + ty + 16 * i;
        if (row < V) {
            float y0, y1, y2, y3;
            upk2(acc[i][0], y0, y1);
            upk2(acc[i][1], y2, y3);
            y0 += bb0; y1 += bb1; y2 += bb2; y3 += bb3;
            *reinterpret_cast<float4*>(&g_Y2[(size_t)row * 64 + c0]) =
                make_float4(y0, y1, y2, y3);
            s0 += y0; s1 += y1; s2 += y2; s3 += y3;
            q0 += y0 * y0; q1 += y1 * y1; q2 += y2 * y2; q3 += y3 * y3;
        }
    }
    atomicAdd(&sSum[c0], s0);     atomicAdd(&sSq[c0], q0);
    atomicAdd(&sSum[c0 + 1], s1); atomicAdd(&sSq[c0 + 1], q1);
    atomicAdd(&sSum[c0 + 2], s2); atomicAdd(&sSq[c0 + 2], q2);
    atomicAdd(&sSum[c0 + 3], s3); atomicAdd(&sSq[c0 + 3], q3);
    __syncthreads();
    if (tid < 64) {
        atomicAdd(&g_stats[128 + tid], sSum[tid]);
        atomicAdd(&g_stats[192 + tid], sSq[tid]);
    }
}

// ---- K = [relu(bn2(Y2)), x_mod] @ Wk + bk ; X = dot(K, Q[seg]) ------------
__global__ __launch_bounds__(256) void k_gemmK(const float* __restrict__ xmod,
                                               const float* __restrict__ Wk,
                                               const float* __restrict__ bk, int V) {
    __shared__ __align__(16) float sW[64 * 64];
    __shared__ __align__(16) float sIn[64 * 64];
    __shared__ __align__(16) float sQ[64 * 64];
    int tid = threadIdx.x;
    int row0 = blockIdx.x * 64;

    // gather Q rows for this tile's segments
    for (int i = tid; i < 64 * 64; i += 256) {
        int r = i >> 6, c = i & 63;
        int row = row0 + r; if (row >= V) row = V - 1;
        sQ[i] = g_Q[(size_t)g_seg[row] * 64 + c];
    }

    int tx = tid & 15, ty = tid >> 4;
    unsigned long long acc[4][2] = {};

    // phase 0: h2 part (Wk rows [0,64))
    for (int i = tid; i < 64 * 64; i += 256) sW[i] = Wk[i];
    for (int i = tid; i < 64 * 64; i += 256) {
        int r = i >> 6, c = i & 63;
        int row = row0 + r;
        float y = (row < V) ? g_Y2[(size_t)row * 64 + c] : 0.f;
        sIn[i] = fmaxf(fmaf(y, __ldg(&g_bn2[c]), __ldg(&g_bn2[64 + c])), 0.f);
    }
    __syncthreads();
    mm_tile<64>(sIn, sW, acc, tx, ty);
    __syncthreads();

    // phase 1: x_mod cols [0,64) (Wk rows [64,128))
    for (int i = tid; i < 64 * 64; i += 256) sW[i] = Wk[64 * 64 + i];
    for (int i = tid; i < 64 * 64; i += 256) {
        int r = i >> 6, c = i & 63;
        int row = row0 + r;
        sIn[i] = (row < V) ? xmod[(size_t)row * 128 + c] : 0.f;
    }
    __syncthreads();
    mm_tile<64>(sIn, sW, acc, tx, ty);
    __syncthreads();

    // phase 2: x_mod cols [64,128) (Wk rows [128,192))
    for (int i = tid; i < 64 * 64; i += 256) sW[i] = Wk[128 * 64 + i];
    for (int i = tid; i < 64 * 64; i += 256) {
        int r = i >> 6, c = i & 63;
        int row = row0 + r;
        sIn[i] = (row < V) ? xmod[(size_t)row * 128 + 64 + c] : 0.f;
    }
    __syncthreads();
    mm_tile<64>(sIn, sW, acc, tx, ty);

    // epilogue: add bias, dot with Q row, reduce over the 16 col-threads
    int c0 = tx * 4;
    float bb0 = bk[c0], bb1 = bk[c0 + 1], bb2 = bk[c0 + 2], bb3 = bk[c0 + 3];
#pragma unroll
    for (int i = 0; i < 4; ++i) {
        float k0, k1, k2, k3;
        upk2(acc[i][0], k0, k1);
        upk2(acc[i][1], k2, k3);
        k0 += bb0; k1 += bb1; k2 += bb2; k3 += bb3;
        const float* q = &sQ[(ty + 16 * i) * 64 + c0];
        float p = k0 * q[0] + k1 * q[1] + k2 * q[2] + k3 * q[3];
        p += __shfl_xor_sync(0xffffffffu, p, 1);
        p += __shfl_xor_sync(0xffffffffu, p, 2);
        p += __shfl_xor_sync(0xffffffffu, p, 4);
        p += __shfl_xor_sync(0xffffffffu, p, 8);
        int row = row0 + ty + 16 * i;
        if (tx == 0 && row < V) g_X[row] = p;
    }
}

// ---- per-segment scaled softmax + weighted max-pool + gate ----------------
__global__ __launch_bounds__(256) void k_pool(const int* __restrict__ csr,
                                              const float* __restrict__ xmod,
                                              float* __restrict__ out,
                                              int N, int hasSeen) {
    int warp = (blockIdx.x * blockDim.x + threadIdx.x) >> 5;
    int lane = threadIdx.x & 31;
    if (warp >= N) return;
    int s = csr[warp], e = csr[warp + 1];
    int cnt = e - s;
    float* orow = out + (size_t)warp * 128;
    if (cnt <= 0) {
        orow[lane] = 0.f; orow[lane + 32] = 0.f;
        orow[lane + 64] = 0.f; orow[lane + 96] = 0.f;
        if (hasSeen && lane == 0) out[(size_t)N * 128 + warp] = 0.f;
        return;
    }
    const float NEG_INF = __int_as_float(0xff800000);
    float m = NEG_INF;
    for (int v = s + lane; v < e; v += 32) m = fmaxf(m, g_X[v]);
#pragma unroll
    for (int o = 16; o; o >>= 1) m = fmaxf(m, __shfl_xor_sync(0xffffffffu, m, o));
    float inv = rsqrtf((float)cnt);
    float ss = 0.f;
    for (int v = s + lane; v < e; v += 32) ss += expf((g_X[v] - m) * inv);
#pragma unroll
    for (int o = 16; o; o >>= 1) ss += __shfl_xor_sync(0xffffffffu, ss, o);
    float denom = ss + 1e-12f;
    float G = tanhf(fmaxf(m, 0.f));
    float p0 = NEG_INF, p1 = NEG_INF, p2 = NEG_INF, p3 = NEG_INF;
    for (int v = s; v < e; ++v) {
        float a = expf((g_X[v] - m) * inv) / denom;
        const float* xr = xmod + (size_t)v * 128;
        p0 = fmaxf(p0, xr[lane] * a);
        p1 = fmaxf(p1, xr[lane + 32] * a);
        p2 = fmaxf(p2, xr[lane + 64] * a);
        p3 = fmaxf(p3, xr[lane + 96] * a);
    }
    orow[lane]      = p0 * G;
    orow[lane + 32] = p1 * G;
    orow[lane + 64] = p2 * G;
    orow[lane + 96] = p3 * G;
    if (hasSeen && lane == 0) out[(size_t)N * 128 + warp] = 1.f;
}

// ---------------------------------------------------------------------------
extern "C" void kernel_launch(void* const* d_in, const int* in_sizes, int n_in,
                              void* d_out, int out_size) {
    const float* x_main = (const float*)d_in[0];
    const float* x_mod  = (const float*)d_in[1];
    const float* x_proj = (const float*)d_in[2];
    const int*   csr    = (const int*)d_in[3];
    const float* Wq = (const float*)d_in[4];
    const float* bq = (const float*)d_in[5];
    const float* W1 = (const float*)d_in[6];
    const float* b1 = (const float*)d_in[7];
    const float* g1 = (const float*)d_in[8];
    const float* be1 = (const float*)d_in[9];
    const float* W2 = (const float*)d_in[10];
    const float* b2 = (const float*)d_in[11];
    const float* g2 = (const float*)d_in[12];
    const float* be2 = (const float*)d_in[13];
    const float* Wk = (const float*)d_in[14];
    const float* bk = (const float*)d_in[15];

    int N = in_sizes[0] / 64;
    int V = in_sizes[1] / 128;
    float* out = (float*)d_out;
    int hasSeen = (out_size >= N * 129) ? 1 : 0;
    float invV = 1.0f / (float)V;

    int vb = (V + 63) / 64;
    int nb = (N + 63) / 64;

    k_zero_stats<<<1, 256>>>();
    k_seg<<<(N + 255) / 256, 256>>>(csr, N);
    k_qgemm<<<nb, 256>>>(x_main, Wq, bq, N);
    k_gemm1<<<vb, 256>>>(x_proj, W1, b1, V);
    k_finalize<<<1, 64>>>(g1, be1, 0, invV);
    k_gemm2<<<vb, 256>>>(W2, b2, V);
    k_finalize<<<1, 64>>>(g2, be2, 1, invV);
    k_gemmK<<<vb, 256>>>(x_mod, Wk, bk, V);
    k_pool<<<(N * 32 + 255) / 256, 256>>>(csr, x_mod, out, N, hasSeen);
}

// round 2
// speedup vs baseline: 1.9880x; 1.9880x over previous
#include <cuda_runtime.h>
#include <math.h>

// ---------------------------------------------------------------------------
// AttentiveBimodalCSRPool — round 2.
//  * mm128x64: 128x64 tile, transposed input in smem, f32x2 FMA, fma-bound.
//  * algebraic fold: X_v = concat(h2,xmod) . (Wk @ q_seg) + bk.q_seg,
//      R = x_main @ (Wq Wk^T) + bq Wk^T   (1.5 G-FMA instead of 12.3)
//  * fused gemm1->bn1->relu->gemm2 (Y1 never in DRAM)
// Pipeline:
//   k_zero_stats, k_seg, k_prep (combine weights),
//   k_stats1 (Y1 batch stats only), bn1 finalize,
//   k_fused12 (x_proj -> Y2 + stats), bn2 finalize,
//   k_R (x_main -> R[N,192]), k_c (c_n = bk.q_n),
//   k_score (X[V]), k_pool (softmax+maxpool+gate)
// ---------------------------------------------------------------------------

#define MAXV 1000000
#define MAXN 125056
typedef unsigned long long ull;

__device__ float g_Y2[(size_t)MAXV * 64];
__device__ float g_R[(size_t)MAXN * 192];
__device__ float g_c[MAXN];
__device__ float g_X[MAXV];
__device__ int   g_seg[MAXV];
__device__ float g_stats[256];    // [sum1(64), sq1(64), sum2(64), sq2(64)]
__device__ float g_bn1[128];      // [scale(64), shift(64)]
__device__ float g_bn2[128];
__device__ float g_Acmb[64 * 192];  // Wq @ Wk^T
__device__ float g_r0[192];         // bq @ Wk^T
__device__ float g_wc[64];          // Wq @ bk
__device__ float g_c0[1];           // bq . bk

// ---- packed f32x2 helpers -------------------------------------------------
__device__ __forceinline__ ull pk2(float lo, float hi) {
    ull r; asm("mov.b64 %0, {%1, %2};" : "=l"(r) : "f"(lo), "f"(hi)); return r;
}
__device__ __forceinline__ ull fma2(ull a, ull b, ull c) {
    ull d; asm("fma.rn.f32x2 %0, %1, %2, %3;" : "=l"(d) : "l"(a), "l"(b), "l"(c));
    return d;
}
__device__ __forceinline__ void upk2(ull v, float& lo, float& hi) {
    asm("mov.b64 {%0, %1}, %2;" : "=f"(lo), "=f"(hi) : "l"(v));
}

// ---- global -> smem transposed tile loader: sXT[k][row], 128 rows ---------
template <int K>
__device__ __forceinline__ void load_tileT(const float* __restrict__ src,
                                           int row0, int limit,
                                           float* __restrict__ sXT, int tid) {
    constexpr int K4 = K / 4;
    for (int t = tid; t < 128 * K4; t += 256) {
        int k4 = t % K4;
        int r  = t / K4;
        int row = row0 + r;
        float4 x = make_float4(0.f, 0.f, 0.f, 0.f);
        if (row < limit) x = *reinterpret_cast<const float4*>(&src[(size_t)row * K + k4 * 4]);
        sXT[(k4 * 4 + 0) * 128 + r] = x.x;
        sXT[(k4 * 4 + 1) * 128 + r] = x.y;
        sXT[(k4 * 4 + 2) * 128 + r] = x.z;
        sXT[(k4 * 4 + 3) * 128 + r] = x.w;
    }
}

// ---- 128-row x 64-col micro-kernel ----------------------------------------
// 256 threads: tx=tid&15 owns cols tx*4..+3; ty=tid>>4 owns rows ty*8..+7.
template <int K>
__device__ __forceinline__ void mm128x64(const float* __restrict__ sXT,  // [K][128]
                                         const float* __restrict__ sW,   // [K][64]
                                         ull acc[8][2], int tx, int ty) {
    const int c0 = tx * 4, r0 = ty * 8;
#pragma unroll 16
    for (int k = 0; k < K; ++k) {
        ulonglong2 w = *reinterpret_cast<const ulonglong2*>(&sW[k * 64 + c0]);
        float4 a0 = *reinterpret_cast<const float4*>(&sXT[k * 128 + r0]);
        float4 a1 = *reinterpret_cast<const float4*>(&sXT[k * 128 + r0 + 4]);
        ull ap;
        ap = pk2(a0.x, a0.x); acc[0][0] = fma2(ap, w.x, acc[0][0]); acc[0][1] = fma2(ap, w.y, acc[0][1]);
        ap = pk2(a0.y, a0.y); acc[1][0] = fma2(ap, w.x, acc[1][0]); acc[1][1] = fma2(ap, w.y, acc[1][1]);
        ap = pk2(a0.z, a0.z); acc[2][0] = fma2(ap, w.x, acc[2][0]); acc[2][1] = fma2(ap, w.y, acc[2][1]);
        ap = pk2(a0.w, a0.w); acc[3][0] = fma2(ap, w.x, acc[3][0]); acc[3][1] = fma2(ap, w.y, acc[3][1]);
        ap = pk2(a1.x, a1.x); acc[4][0] = fma2(ap, w.x, acc[4][0]); acc[4][1] = fma2(ap, w.y, acc[4][1]);
        ap = pk2(a1.y, a1.y); acc[5][0] = fma2(ap, w.x, acc[5][0]); acc[5][1] = fma2(ap, w.y, acc[5][1]);
        ap = pk2(a1.z, a1.z); acc[6][0] = fma2(ap, w.x, acc[6][0]); acc[6][1] = fma2(ap, w.y, acc[6][1]);
        ap = pk2(a1.w, a1.w); acc[7][0] = fma2(ap, w.x, acc[7][0]); acc[7][1] = fma2(ap, w.y, acc[7][1]);
    }
}

// ---- block-wide stats reduction (sum + sumsq per col), sPart = 8*128 floats
__device__ __forceinline__ void stats_reduce(float s[4], float q[4], int tid,
                                             float* sPart,
                                             float* gsum, float* gsq) {
    int lane = tid & 31, wrp = tid >> 5;
#pragma unroll
    for (int j = 0; j < 4; ++j) {
        s[j] += __shfl_xor_sync(0xffffffffu, s[j], 16);
        q[j] += __shfl_xor_sync(0xffffffffu, q[j], 16);
    }
    if (lane < 16) {
        int c0 = (tid & 15) * 4;
#pragma unroll
        for (int j = 0; j < 4; ++j) {
            sPart[wrp * 128 + c0 + j] = s[j];
            sPart[wrp * 128 + 64 + c0 + j] = q[j];
        }
    }
    __syncthreads();
    if (tid < 128) {
        float t = 0.f;
#pragma unroll
        for (int w = 0; w < 8; ++w) t += sPart[w * 128 + tid];
        if (tid < 64) atomicAdd(gsum + tid, t);
        else          atomicAdd(gsq + (tid - 64), t);
    }
}

// ---------------------------------------------------------------------------
__global__ void k_zero_stats() { if (threadIdx.x < 256) g_stats[threadIdx.x] = 0.f; }

__global__ void k_seg(const int* __restrict__ csr, int N) {
    int n = blockIdx.x * blockDim.x + threadIdx.x;
    if (n < N) {
        int s = csr[n], e = csr[n + 1];
        for (int v = s; v < e; ++v) g_seg[v] = n;
    }
}

// ---- combined weights: Acmb = Wq @ Wk^T, r0 = bq @ Wk^T, wc = Wq@bk, c0 ---
__global__ __launch_bounds__(256) void k_prep(const float* __restrict__ Wq,
                                              const float* __restrict__ bq,
                                              const float* __restrict__ Wk,
                                              const float* __restrict__ bk) {
    int tid = threadIdx.x;
    for (int idx = tid; idx < 64 * 192; idx += 256) {
        int i = idx / 192, j = idx % 192;
        float a = 0.f;
#pragma unroll 8
        for (int s = 0; s < 64; ++s)
            a = fmaf(__ldg(&Wq[i * 64 + s]), __ldg(&Wk[j * 64 + s]), a);
        g_Acmb[i * 192 + j] = a;
    }
    if (tid < 192) {
        float a = 0.f;
#pragma unroll 8
        for (int s = 0; s < 64; ++s) a = fmaf(__ldg(&bq[s]), __ldg(&Wk[tid * 64 + s]), a);
        g_r0[tid] = a;
    }
    if (tid < 64) {
        float a = 0.f;
#pragma unroll 8
        for (int s = 0; s < 64; ++s) a = fmaf(__ldg(&Wq[tid * 64 + s]), __ldg(&bk[s]), a);
        g_wc[tid] = a;
    }
    if (tid == 0) {
        float a = 0.f;
        for (int s = 0; s < 64; ++s) a = fmaf(bq[s], bk[s], a);
        g_c0[0] = a;
    }
}

// ---- stage-1 batch stats only (Y1 = x_proj@W1 + b1) -----------------------
__global__ __launch_bounds__(256) void k_stats1(const float* __restrict__ xproj,
                                                const float* __restrict__ W,
                                                const float* __restrict__ b, int V) {
    __shared__ __align__(16) float sXT[32 * 128];
    __shared__ __align__(16) float sW[32 * 64];
    __shared__ float sPart[8 * 128];
    int tid = threadIdx.x;
    int row0 = blockIdx.x * 128;
    load_tileT<32>(xproj, row0, V, sXT, tid);
    for (int i = tid; i < 32 * 64; i += 256) sW[i] = W[i];
    __syncthreads();
    int tx = tid & 15, ty = tid >> 4;
    ull acc[8][2] = {};
    mm128x64<32>(sXT, sW, acc, tx, ty);
    int c0 = tx * 4;
    float b0 = b[c0], b1v = b[c0 + 1], b2v = b[c0 + 2], b3 = b[c0 + 3];
    float s[4] = {}, q[4] = {};
#pragma unroll
    for (int i = 0; i < 8; ++i) {
        int row = row0 + ty * 8 + i;
        if (row < V) {
            float y0, y1, y2, y3;
            upk2(acc[i][0], y0, y1); upk2(acc[i][1], y2, y3);
            y0 += b0; y1 += b1v; y2 += b2v; y3 += b3;
            s[0] += y0; s[1] += y1; s[2] += y2; s[3] += y3;
            q[0] += y0 * y0; q[1] += y1 * y1; q[2] += y2 * y2; q[3] += y3 * y3;
        }
    }
    stats_reduce(s, q, tid, sPart, &g_stats[0], &g_stats[64]);
}

__global__ void k_finalize(const float* __restrict__ gg,
                           const float* __restrict__ bb, int stage, float invV) {
    int c = threadIdx.x;
    if (c >= 64) return;
    float* bn = stage ? g_bn2 : g_bn1;
    int off = stage ? 128 : 0;
    float mean = g_stats[off + c] * invV;
    float var  = g_stats[off + 64 + c] * invV - mean * mean;
    float sc = gg[c] / sqrtf(var + 1e-5f);
    bn[c] = sc;
    bn[64 + c] = bb[c] - mean * sc;
}

// ---- fused: x_proj -> Y1 -> bn1/relu -> @W2 -> Y2 (+stats2) ---------------
__global__ __launch_bounds__(256) void k_fused12(const float* __restrict__ xproj,
                                                 const float* __restrict__ W1,
                                                 const float* __restrict__ b1,
                                                 const float* __restrict__ W2,
                                                 const float* __restrict__ b2, int V) {
    __shared__ __align__(16) float smA[64 * 128];   // stage1: sXT(16K)+sW1(8K); stage2: h1T(32K); then stats
    __shared__ __align__(16) float sW2[64 * 64];
    float* sXT = smA;
    float* sW1 = smA + 32 * 128;
    int tid = threadIdx.x;
    int row0 = blockIdx.x * 128;

    load_tileT<32>(xproj, row0, V, sXT, tid);
    for (int i = tid; i < 32 * 64; i += 256) sW1[i] = W1[i];
    for (int i = tid; i < 64 * 64; i += 256) sW2[i] = W2[i];
    __syncthreads();

    int tx = tid & 15, ty = tid >> 4;
    int c0 = tx * 4, r0 = ty * 8;
    ull acc[8][2] = {};
    mm128x64<32>(sXT, sW1, acc, tx, ty);

    // bn1 + relu
    float bb[4], sc[4], sh[4];
#pragma unroll
    for (int j = 0; j < 4; ++j) {
        bb[j] = b1[c0 + j];
        sc[j] = g_bn1[c0 + j];
        sh[j] = g_bn1[64 + c0 + j];
    }
    float h[8][4];
#pragma unroll
    for (int i = 0; i < 8; ++i) {
        float y0, y1, y2, y3;
        upk2(acc[i][0], y0, y1); upk2(acc[i][1], y2, y3);
        h[i][0] = fmaxf(fmaf(y0 + bb[0], sc[0], sh[0]), 0.f);
        h[i][1] = fmaxf(fmaf(y1 + bb[1], sc[1], sh[1]), 0.f);
        h[i][2] = fmaxf(fmaf(y2 + bb[2], sc[2], sh[2]), 0.f);
        h[i][3] = fmaxf(fmaf(y3 + bb[3], sc[3], sh[3]), 0.f);
    }
    __syncthreads();   // done reading sXT/sW1

    // write h1T[k2=c][row] (smA reused)
    float* h1T = smA;
#pragma unroll
    for (int j = 0; j < 4; ++j) {
        *reinterpret_cast<float4*>(&h1T[(c0 + j) * 128 + r0]) =
            make_float4(h[0][j], h[1][j], h[2][j], h[3][j]);
        *reinterpret_cast<float4*>(&h1T[(c0 + j) * 128 + r0 + 4]) =
            make_float4(h[4][j], h[5][j], h[6][j], h[7][j]);
    }
    __syncthreads();

    ull acc2[8][2] = {};
    mm128x64<64>(h1T, sW2, acc2, tx, ty);
    __syncthreads();   // h1T dead; smA becomes stats scratch

    float b20 = b2[c0], b21 = b2[c0 + 1], b22 = b2[c0 + 2], b23 = b2[c0 + 3];
    float s[4] = {}, q[4] = {};
#pragma unroll
    for (int i = 0; i < 8; ++i) {
        int row = row0 + r0 + i;
        float y0, y1, y2, y3;
        upk2(acc2[i][0], y0, y1); upk2(acc2[i][1], y2, y3);
        y0 += b20; y1 += b21; y2 += b22; y3 += b23;
        if (row < V) {
            *reinterpret_cast<float4*>(&g_Y2[(size_t)row * 64 + c0]) =
                make_float4(y0, y1, y2, y3);
            s[0] += y0; s[1] += y1; s[2] += y2; s[3] += y3;
            q[0] += y0 * y0; q[1] += y1 * y1; q[2] += y2 * y2; q[3] += y3 * y3;
        }
    }
    stats_reduce(s, q, tid, smA, &g_stats[128], &g_stats[192]);
}

// ---- R = x_main @ Acmb + r0  (N x 192, col-tiles of 64) -------------------
__global__ __launch_bounds__(256) void k_R(const float* __restrict__ xmain, int N) {
    __shared__ __align__(16) float sXT[64 * 128];
    __shared__ __align__(16) float sW[64 * 64];
    int tid = threadIdx.x;
    int row0 = blockIdx.x * 128;
    int jt = blockIdx.y;            // col tile 0..2
    load_tileT<64>(xmain, row0, N, sXT, tid);
    for (int i = tid; i < 64 * 64; i += 256) {
        int k = i >> 6, c = i & 63;
        sW[i] = g_Acmb[k * 192 + jt * 64 + c];
    }
    __syncthreads();
    int tx = tid & 15, ty = tid >> 4;
    int c0 = tx * 4, r0 = ty * 8;
    ull acc[8][2] = {};
    mm128x64<64>(sXT, sW, acc, tx, ty);
    float b0 = g_r0[jt * 64 + c0], b1 = g_r0[jt * 64 + c0 + 1];
    float b2 = g_r0[jt * 64 + c0 + 2], b3 = g_r0[jt * 64 + c0 + 3];
#pragma unroll
    for (int i = 0; i < 8; ++i) {
        int row = row0 + r0 + i;
        if (row < N) {
            float y0, y1, y2, y3;
            upk2(acc[i][0], y0, y1); upk2(acc[i][1], y2, y3);
            *reinterpret_cast<float4*>(&g_R[(size_t)row * 192 + jt * 64 + c0]) =
                make_float4(y0 + b0, y1 + b1, y2 + b2, y3 + b3);
        }
    }
}

// ---- c_n = bk . q_n = x_main_n . wc + c0  (warp per n) --------------------
__global__ __launch_bounds__(256) void k_c(const float* __restrict__ xmain, int N) {
    int w = (blockIdx.x * blockDim.x + threadIdx.x) >> 5;
    int l = threadIdx.x & 31;
    if (w >= N) return;
    float p = xmain[(size_t)w * 64 + l] * g_wc[l]
            + xmain[(size_t)w * 64 + 32 + l] * g_wc[32 + l];
#pragma unroll
    for (int o = 16; o; o >>= 1) p += __shfl_xor_sync(0xffffffffu, p, o);
    if (l == 0) g_c[w] = p + g_c0[0];
}

// ---- X_v = h2_v . R_seg[0:64] + xmod_v . R_seg[64:192] + c_seg ------------
__global__ __launch_bounds__(256) void k_score(const float* __restrict__ xmod, int V) {
    int w = (blockIdx.x * blockDim.x + threadIdx.x) >> 5;
    int l = threadIdx.x & 31;
    if (w >= V) return;
    int sg = g_seg[w];
    const float* R = g_R + (size_t)sg * 192;
    float p = 0.f;
#pragma unroll
    for (int j = 0; j < 2; ++j) {
        int c = l + 32 * j;
        float y = g_Y2[(size_t)w * 64 + c];
        float h = fmaxf(fmaf(y, g_bn2[c], g_bn2[64 + c]), 0.f);
        p = fmaf(h, __ldg(&R[c]), p);
    }
#pragma unroll
    for (int j = 0; j < 4; ++j) {
        int c = l + 32 * j;
        p = fmaf(xmod[(size_t)w * 128 + c], __ldg(&R[64 + c]), p);
    }
#pragma unroll
    for (int o = 16; o; o >>= 1) p += __shfl_xor_sync(0xffffffffu, p, o);
    if (l == 0) g_X[w] = p + g_c[sg];
}

// ---- per-segment scaled softmax + weighted max-pool + gate ----------------
__global__ __launch_bounds__(256) void k_pool(const int* __restrict__ csr,
                                              const float* __restrict__ xmod,
                                              float* __restrict__ out,
                                              int N, int hasSeen) {
    int warp = (blockIdx.x * blockDim.x + threadIdx.x) >> 5;
    int lane = threadIdx.x & 31;
    if (warp >= N) return;
    int s = csr[warp], e = csr[warp + 1];
    int cnt = e - s;
    float* orow = out + (size_t)warp * 128;
    if (cnt <= 0) {
        orow[lane] = 0.f; orow[lane + 32] = 0.f;
        orow[lane + 64] = 0.f; orow[lane + 96] = 0.f;
        if (hasSeen && lane == 0) out[(size_t)N * 128 + warp] = 0.f;
        return;
    }
    const float NEG_INF = __int_as_float(0xff800000);
    float m = NEG_INF;
    for (int v = s + lane; v < e; v += 32) m = fmaxf(m, g_X[v]);
#pragma unroll
    for (int o = 16; o; o >>= 1) m = fmaxf(m, __shfl_xor_sync(0xffffffffu, m, o));
    float inv = rsqrtf((float)cnt);
    float ss = 0.f;
    for (int v = s + lane; v < e; v += 32) ss += expf((g_X[v] - m) * inv);
#pragma unroll
    for (int o = 16; o; o >>= 1) ss += __shfl_xor_sync(0xffffffffu, ss, o);
    float denom = ss + 1e-12f;
    float G = tanhf(fmaxf(m, 0.f));
    float p0 = NEG_INF, p1 = NEG_INF, p2 = NEG_INF, p3 = NEG_INF;
    for (int v = s; v < e; ++v) {
        float a = expf((g_X[v] - m) * inv) / denom;
        const float* xr = xmod + (size_t)v * 128;
        p0 = fmaxf(p0, xr[lane] * a);
        p1 = fmaxf(p1, xr[lane + 32] * a);
        p2 = fmaxf(p2, xr[lane + 64] * a);
        p3 = fmaxf(p3, xr[lane + 96] * a);
    }
    orow[lane]      = p0 * G;
    orow[lane + 32] = p1 * G;
    orow[lane + 64] = p2 * G;
    orow[lane + 96] = p3 * G;
    if (hasSeen && lane == 0) out[(size_t)N * 128 + warp] = 1.f;
}

// ---------------------------------------------------------------------------
extern "C" void kernel_launch(void* const* d_in, const int* in_sizes, int n_in,
                              void* d_out, int out_size) {
    const float* x_main = (const float*)d_in[0];
    const float* x_mod  = (const float*)d_in[1];
    const float* x_proj = (const float*)d_in[2];
    const int*   csr    = (const int*)d_in[3];
    const float* Wq = (const float*)d_in[4];
    const float* bq = (const float*)d_in[5];
    const float* W1 = (const float*)d_in[6];
    const float* b1 = (const float*)d_in[7];
    const float* g1 = (const float*)d_in[8];
    const float* be1 = (const float*)d_in[9];
    const float* W2 = (const float*)d_in[10];
    const float* b2 = (const float*)d_in[11];
    const float* g2 = (const float*)d_in[12];
    const float* be2 = (const float*)d_in[13];
    const float* Wk = (const float*)d_in[14];
    const float* bk = (const float*)d_in[15];

    int N = in_sizes[0] / 64;
    int V = in_sizes[1] / 128;
    float* out = (float*)d_out;
    int hasSeen = (out_size >= N * 129) ? 1 : 0;
    float invV = 1.0f / (float)V;

    int vb128 = (V + 127) / 128;
    int nb128 = (N + 127) / 128;

    k_zero_stats<<<1, 256>>>();
    k_seg<<<(N + 255) / 256, 256>>>(csr, N);
    k_prep<<<1, 256>>>(Wq, bq, Wk, bk);
    k_stats1<<<vb128, 256>>>(x_proj, W1, b1, V);
    k_finalize<<<1, 64>>>(g1, be1, 0, invV);
    k_fused12<<<vb128, 256>>>(x_proj, W1, b1, W2, b2, V);
    k_finalize<<<1, 64>>>(g2, be2, 1, invV);
    {
        dim3 g(nb128, 3);
        k_R<<<g, 256>>>(x_main, N);
    }
    k_c<<<(N * 32 + 255) / 256, 256>>>(x_main, N);
    k_score<<<(V * 32 + 255) / 256, 256>>>(x_mod, V);
    k_pool<<<(N * 32 + 255) / 256, 256>>>(csr, x_mod, out, N, hasSeen);
}

// round 3
// speedup vs baseline: 2.6872x; 1.3518x over previous
#include <cuda_runtime.h>
#include <math.h>

// ---------------------------------------------------------------------------
// AttentiveBimodalCSRPool — round 3.
//  * row-major smem A-tiles with odd LD (33): conflict-free loader stores and
//    conflict-free broadcast scalar A-loads in the micro-kernel.
//  * fused12: stage1 GEMM -> bn1/relu -> h1T (transposed, f4 stores) -> stage2.
//  * k_prep moved to smem tiles (was LDG-throughput bound single block).
//  * algebraic fold of the score GEMM through the weights (as round 2).
// ---------------------------------------------------------------------------

#define MAXV 1000000
#define MAXN 125056
typedef unsigned long long ull;

__device__ float g_Y2[(size_t)MAXV * 64];
__device__ float g_R[(size_t)MAXN * 192];
__device__ float g_c[MAXN];
__device__ float g_X[MAXV];
__device__ int   g_seg[MAXV];
__device__ float g_stats[256];    // [sum1(64), sq1(64), sum2(64), sq2(64)]
__device__ float g_bn1[128];      // [scale(64), shift(64)]
__device__ float g_bn2[128];
__device__ float g_Acmb[64 * 192];  // Wq @ Wk^T
__device__ float g_r0[192];         // bq @ Wk^T
__device__ float g_wc[64];          // Wq @ bk
__device__ float g_c0[1];           // bq . bk

// ---- packed f32x2 helpers -------------------------------------------------
__device__ __forceinline__ ull pk2(float lo, float hi) {
    ull r; asm("mov.b64 %0, {%1, %2};" : "=l"(r) : "f"(lo), "f"(hi)); return r;
}
__device__ __forceinline__ ull fma2(ull a, ull b, ull c) {
    ull d; asm("fma.rn.f32x2 %0, %1, %2, %3;" : "=l"(d) : "l"(a), "l"(b), "l"(c));
    return d;
}
__device__ __forceinline__ void upk2(ull v, float& lo, float& hi) {
    asm("mov.b64 {%0, %1}, %2;" : "=f"(lo), "=f"(hi) : "l"(v));
}

// ---- row-major tile loader: sX[r][k] with LD=K+1 (odd), conflict-free -----
// src rows have srcStride floats; loads K consecutive cols at srcOff.
template <int K, int LD, int NT>
__device__ __forceinline__ void load_rm(const float* __restrict__ src,
                                        int row0, int limit,
                                        int srcStride, int srcOff,
                                        float* __restrict__ sX, int tid) {
    constexpr int K4 = K / 4;
    for (int t = tid; t < 128 * K4; t += NT) {
        int c4 = t % K4;
        int r  = t / K4;
        int row = row0 + r;
        float4 x = make_float4(0.f, 0.f, 0.f, 0.f);
        if (row < limit)
            x = *reinterpret_cast<const float4*>(&src[(size_t)row * srcStride + srcOff + c4 * 4]);
        float* d = &sX[r * LD + c4 * 4];
        d[0] = x.x; d[1] = x.y; d[2] = x.z; d[3] = x.w;
    }
}

// ---- 128x64 tile micro-kernel, A row-major sX[r*LD+k] ---------------------
// 128 threads: tx=tid&7 -> cols tx*8..+7 ; ty=tid>>3 -> rows ty*8..+7.
template <int K, int LD>
__device__ __forceinline__ void mm8_rm(const float* __restrict__ sX,
                                       const float* __restrict__ sW,  // [K][64]
                                       ull acc[8][4], int tx, int ty) {
    const int c0 = tx * 8, r0 = ty * 8;
#pragma unroll 8
    for (int k = 0; k < K; ++k) {
        ulonglong2 w0 = *reinterpret_cast<const ulonglong2*>(&sW[k * 64 + c0]);
        ulonglong2 w1 = *reinterpret_cast<const ulonglong2*>(&sW[k * 64 + c0 + 4]);
#pragma unroll
        for (int i = 0; i < 8; ++i) {
            float a = sX[(r0 + i) * LD + k];
            ull ap = pk2(a, a);
            acc[i][0] = fma2(ap, w0.x, acc[i][0]);
            acc[i][1] = fma2(ap, w0.y, acc[i][1]);
            acc[i][2] = fma2(ap, w1.x, acc[i][2]);
            acc[i][3] = fma2(ap, w1.y, acc[i][3]);
        }
    }
}

// ---- same but A transposed: sXT[k*128 + r] (for h1T) ----------------------
template <int K>
__device__ __forceinline__ void mm8_cm(const float* __restrict__ sXT,
                                       const float* __restrict__ sW,
                                       ull acc[8][4], int tx, int ty) {
    const int c0 = tx * 8, r0 = ty * 8;
#pragma unroll 8
    for (int k = 0; k < K; ++k) {
        ulonglong2 w0 = *reinterpret_cast<const ulonglong2*>(&sW[k * 64 + c0]);
        ulonglong2 w1 = *reinterpret_cast<const ulonglong2*>(&sW[k * 64 + c0 + 4]);
#pragma unroll
        for (int i = 0; i < 8; ++i) {
            float a = sXT[k * 128 + r0 + i];
            ull ap = pk2(a, a);
            acc[i][0] = fma2(ap, w0.x, acc[i][0]);
            acc[i][1] = fma2(ap, w0.y, acc[i][1]);
            acc[i][2] = fma2(ap, w1.x, acc[i][2]);
            acc[i][3] = fma2(ap, w1.y, acc[i][3]);
        }
    }
}

// ---- block stats reduction for 128-thread / 8-col-per-thread layout -------
__device__ __forceinline__ void stats_reduce8(float s[8], float q[8], int tid,
                                              float* sPart /*4*128*/,
                                              float* gsum, float* gsq) {
    int lane = tid & 31, wrp = tid >> 5;
#pragma unroll
    for (int j = 0; j < 8; ++j) {
        s[j] += __shfl_xor_sync(0xffffffffu, s[j], 8);
        s[j] += __shfl_xor_sync(0xffffffffu, s[j], 16);
        q[j] += __shfl_xor_sync(0xffffffffu, q[j], 8);
        q[j] += __shfl_xor_sync(0xffffffffu, q[j], 16);
    }
    if (lane < 8) {
        int c0 = lane * 8;
#pragma unroll
        for (int j = 0; j < 8; ++j) {
            sPart[wrp * 128 + c0 + j] = s[j];
            sPart[wrp * 128 + 64 + c0 + j] = q[j];
        }
    }
    __syncthreads();
    if (tid < 128) {
        float t = 0.f;
#pragma unroll
        for (int w = 0; w < 4; ++w) t += sPart[w * 128 + tid];
        if (tid < 64) atomicAdd(gsum + tid, t);
        else          atomicAdd(gsq + (tid - 64), t);
    }
}

// ---------------------------------------------------------------------------
__global__ void k_zero_stats() { if (threadIdx.x < 256) g_stats[threadIdx.x] = 0.f; }

__global__ void k_seg(const int* __restrict__ csr, int N) {
    int n = blockIdx.x * blockDim.x + threadIdx.x;
    if (n < N) {
        int s = csr[n], e = csr[n + 1];
        for (int v = s; v < e; ++v) g_seg[v] = n;
    }
}

// ---- combined weights (smem-tiled): Acmb = Wq@Wk^T, r0, wc, c0 ------------
__global__ __launch_bounds__(256) void k_prep(const float* __restrict__ Wq,
                                              const float* __restrict__ bq,
                                              const float* __restrict__ Wk,
                                              const float* __restrict__ bk) {
    __shared__ float sWq[64 * 64];      // Wq[i][s]
    __shared__ float sWk[64 * 65];      // chunk of Wk rows, padded LD=65
    __shared__ float sbq[64], sbk[64];
    int tid = threadIdx.x;
    for (int i = tid; i < 64 * 64; i += 256) sWq[i] = Wq[i];
    if (tid < 64) { sbq[tid] = bq[tid]; sbk[tid] = bk[tid]; }
    __syncthreads();
    int irow = tid >> 6;       // 0..3
    int jl   = tid & 63;       // 0..63
    for (int cc = 0; cc < 3; ++cc) {
        __syncthreads();
        for (int t = tid; t < 64 * 64; t += 256) {
            int jj = t >> 6, s = t & 63;
            sWk[jj * 65 + s] = Wk[(cc * 64 + jj) * 64 + s];
        }
        __syncthreads();
#pragma unroll 4
        for (int it = 0; it < 16; ++it) {
            int ii = it * 4 + irow;
            float a = 0.f;
#pragma unroll 8
            for (int s = 0; s < 64; ++s)
                a = fmaf(sWq[ii * 64 + s], sWk[jl * 65 + s], a);
            g_Acmb[ii * 192 + cc * 64 + jl] = a;
        }
        if (tid < 64) {
            float a = 0.f;
#pragma unroll 8
            for (int s = 0; s < 64; ++s) a = fmaf(sbq[s], sWk[tid * 65 + s], a);
            g_r0[cc * 64 + tid] = a;
        }
    }
    if (tid < 64) {
        float a = 0.f;
#pragma unroll 8
        for (int s = 0; s < 64; ++s) a = fmaf(sWq[tid * 64 + s], sbk[s], a);
        g_wc[tid] = a;
    }
    if (tid == 0) {
        float a = 0.f;
        for (int s = 0; s < 64; ++s) a = fmaf(sbq[s], sbk[s], a);
        g_c0[0] = a;
    }
}

// ---- stage-1 batch stats (Y1 = x_proj@W1 + b1) ----------------------------
__global__ __launch_bounds__(128) void k_stats1(const float* __restrict__ xproj,
                                                const float* __restrict__ W,
                                                const float* __restrict__ b, int V) {
    __shared__ __align__(16) float sX[128 * 33];
    __shared__ __align__(16) float sW[32 * 64];
    __shared__ float sPart[4 * 128];
    int tid = threadIdx.x;
    int row0 = blockIdx.x * 128;
    load_rm<32, 33, 128>(xproj, row0, V, 32, 0, sX, tid);
    for (int i = tid; i < 32 * 64; i += 128) sW[i] = W[i];
    __syncthreads();
    int tx = tid & 7, ty = tid >> 3;
    ull acc[8][4] = {};
    mm8_rm<32, 33>(sX, sW, acc, tx, ty);
    int c0 = tx * 8;
    float bb[8];
#pragma unroll
    for (int j = 0; j < 8; ++j) bb[j] = b[c0 + j];
    float s[8] = {}, q[8] = {};
#pragma unroll
    for (int i = 0; i < 8; ++i) {
        int row = row0 + ty * 8 + i;
        if (row < V) {
#pragma unroll
            for (int jp = 0; jp < 4; ++jp) {
                float y0, y1;
                upk2(acc[i][jp], y0, y1);
                y0 += bb[jp * 2]; y1 += bb[jp * 2 + 1];
                s[jp * 2] += y0; s[jp * 2 + 1] += y1;
                q[jp * 2] += y0 * y0; q[jp * 2 + 1] += y1 * y1;
            }
        }
    }
    stats_reduce8(s, q, tid, sPart, &g_stats[0], &g_stats[64]);
}

__global__ void k_finalize(const float* __restrict__ gg,
                           const float* __restrict__ bb, int stage, float invV) {
    int c = threadIdx.x;
    if (c >= 64) return;
    float* bn = stage ? g_bn2 : g_bn1;
    int off = stage ? 128 : 0;
    float mean = g_stats[off + c] * invV;
    float var  = g_stats[off + 64 + c] * invV - mean * mean;
    float sc = gg[c] / sqrtf(var + 1e-5f);
    bn[c] = sc;
    bn[64 + c] = bb[c] - mean * sc;
}

// ---- fused: x_proj -> Y1 -> bn1/relu -> @W2 -> Y2 (+stats2) ---------------
__global__ __launch_bounds__(128) void k_fused12(const float* __restrict__ xproj,
                                                 const float* __restrict__ b1,
                                                 const float* __restrict__ W1,
                                                 const float* __restrict__ W2,
                                                 const float* __restrict__ b2, int V) {
    // union region: stage1 [sX 128*33 | sW1 32*64] ; stage2 h1T 64*128 ; stats
    __shared__ __align__(16) float smA[64 * 128];
    __shared__ __align__(16) float sW2[64 * 64];
    float* sX  = smA;
    float* sW1 = smA + 128 * 33;          // 4224..6271  (<8192)
    float* h1T = smA;
    int tid = threadIdx.x;
    int row0 = blockIdx.x * 128;

    load_rm<32, 33, 128>(xproj, row0, V, 32, 0, sX, tid);
    for (int i = tid; i < 32 * 64; i += 128) sW1[i] = W1[i];
    for (int i = tid; i < 64 * 64; i += 128) sW2[i] = W2[i];
    __syncthreads();

    int tx = tid & 7, ty = tid >> 3;
    int c0 = tx * 8, r0 = ty * 8;
    ull acc[8][4] = {};
    mm8_rm<32, 33>(sX, sW1, acc, tx, ty);

    // bn1 + relu into registers
    float bb[8], sc[8], sh[8];
#pragma unroll
    for (int j = 0; j < 8; ++j) {
        bb[j] = b1[c0 + j];
        sc[j] = g_bn1[c0 + j];
        sh[j] = g_bn1[64 + c0 + j];
    }
    float h[8][8];
#pragma unroll
    for (int i = 0; i < 8; ++i) {
#pragma unroll
        for (int jp = 0; jp < 4; ++jp) {
            float y0, y1;
            upk2(acc[i][jp], y0, y1);
            h[i][jp * 2]     = fmaxf(fmaf(y0 + bb[jp * 2],     sc[jp * 2],     sh[jp * 2]),     0.f);
            h[i][jp * 2 + 1] = fmaxf(fmaf(y1 + bb[jp * 2 + 1], sc[jp * 2 + 1], sh[jp * 2 + 1]), 0.f);
        }
    }
    __syncthreads();   // sX/sW1 dead

    // store transposed h1T[c][r] with float4 (one-time)
#pragma unroll
    for (int j = 0; j < 8; ++j) {
        *reinterpret_cast<float4*>(&h1T[(c0 + j) * 128 + r0]) =
            make_float4(h[0][j], h[1][j], h[2][j], h[3][j]);
        *reinterpret_cast<float4*>(&h1T[(c0 + j) * 128 + r0 + 4]) =
            make_float4(h[4][j], h[5][j], h[6][j], h[7][j]);
    }
    __syncthreads();

    ull acc2[8][4] = {};
    mm8_cm<64>(h1T, sW2, acc2, tx, ty);
    __syncthreads();   // h1T dead -> stats scratch

    float b2v[8];
#pragma unroll
    for (int j = 0; j < 8; ++j) b2v[j] = b2[c0 + j];
    float s[8] = {}, q[8] = {};
#pragma unroll
    for (int i = 0; i < 8; ++i) {
        int row = row0 + r0 + i;
        float y[8];
#pragma unroll
        for (int jp = 0; jp < 4; ++jp) {
            upk2(acc2[i][jp], y[jp * 2], y[jp * 2 + 1]);
            y[jp * 2] += b2v[jp * 2]; y[jp * 2 + 1] += b2v[jp * 2 + 1];
        }
        if (row < V) {
            *reinterpret_cast<float4*>(&g_Y2[(size_t)row * 64 + c0]) =
                make_float4(y[0], y[1], y[2], y[3]);
            *reinterpret_cast<float4*>(&g_Y2[(size_t)row * 64 + c0 + 4]) =
                make_float4(y[4], y[5], y[6], y[7]);
#pragma unroll
            for (int j = 0; j < 8; ++j) { s[j] += y[j]; q[j] += y[j] * y[j]; }
        }
    }
    stats_reduce8(s, q, tid, smA, &g_stats[128], &g_stats[192]);
}

// ---- R = x_main @ Acmb + r0  (N x 192, col tiles of 64, K split 2x32) -----
__global__ __launch_bounds__(128) void k_R(const float* __restrict__ xmain, int N) {
    __shared__ __align__(16) float sX[128 * 33];
    __shared__ __align__(16) float sW[64 * 64];
    int tid = threadIdx.x;
    int row0 = blockIdx.x * 128;
    int jt = blockIdx.y;            // col tile 0..2
    for (int i = tid; i < 64 * 64; i += 128) {
        int k = i >> 6, c = i & 63;
        sW[i] = g_Acmb[k * 192 + jt * 64 + c];
    }
    int tx = tid & 7, ty = tid >> 3;
    ull acc[8][4] = {};
    // half 1: cols 0..31
    load_rm<32, 33, 128>(xmain, row0, N, 64, 0, sX, tid);
    __syncthreads();
    mm8_rm<32, 33>(sX, sW, acc, tx, ty);
    __syncthreads();
    // half 2: cols 32..63
    load_rm<32, 33, 128>(xmain, row0, N, 64, 32, sX, tid);
    __syncthreads();
    mm8_rm<32, 33>(sX, sW + 32 * 64, acc, tx, ty);

    int c0 = tx * 8, r0 = ty * 8;
    float bb[8];
#pragma unroll
    for (int j = 0; j < 8; ++j) bb[j] = g_r0[jt * 64 + c0 + j];
#pragma unroll
    for (int i = 0; i < 8; ++i) {
        int row = row0 + r0 + i;
        if (row < N) {
            float y[8];
#pragma unroll
            for (int jp = 0; jp < 4; ++jp) {
                upk2(acc[i][jp], y[jp * 2], y[jp * 2 + 1]);
                y[jp * 2] += bb[jp * 2]; y[jp * 2 + 1] += bb[jp * 2 + 1];
            }
            *reinterpret_cast<float4*>(&g_R[(size_t)row * 192 + jt * 64 + c0]) =
                make_float4(y[0], y[1], y[2], y[3]);
            *reinterpret_cast<float4*>(&g_R[(size_t)row * 192 + jt * 64 + c0 + 4]) =
                make_float4(y[4], y[5], y[6], y[7]);
        }
    }
}

// ---- c_n = bk . q_n = x_main_n . wc + c0  (warp per n) --------------------
__global__ __launch_bounds__(256) void k_c(const float* __restrict__ xmain, int N) {
    int w = (blockIdx.x * blockDim.x + threadIdx.x) >> 5;
    int l = threadIdx.x & 31;
    if (w >= N) return;
    float p = xmain[(size_t)w * 64 + l] * g_wc[l]
            + xmain[(size_t)w * 64 + 32 + l] * g_wc[32 + l];
#pragma unroll
    for (int o = 16; o; o >>= 1) p += __shfl_xor_sync(0xffffffffu, p, o);
    if (l == 0) g_c[w] = p + g_c0[0];
}

// ---- X_v = h2_v . R_seg[0:64] + xmod_v . R_seg[64:192] + c_seg ------------
__global__ __launch_bounds__(256) void k_score(const float* __restrict__ xmod, int V) {
    int w = (blockIdx.x * blockDim.x + threadIdx.x) >> 5;
    int l = threadIdx.x & 31;
    if (w >= V) return;
    int sg = g_seg[w];
    const float* R = g_R + (size_t)sg * 192;
    float p = 0.f;
#pragma unroll
    for (int j = 0; j < 2; ++j) {
        int c = l + 32 * j;
        float y = g_Y2[(size_t)w * 64 + c];
        float h = fmaxf(fmaf(y, g_bn2[c], g_bn2[64 + c]), 0.f);
        p = fmaf(h, __ldg(&R[c]), p);
    }
#pragma unroll
    for (int j = 0; j < 4; ++j) {
        int c = l + 32 * j;
        p = fmaf(xmod[(size_t)w * 128 + c], __ldg(&R[64 + c]), p);
    }
#pragma unroll
    for (int o = 16; o; o >>= 1) p += __shfl_xor_sync(0xffffffffu, p, o);
    if (l == 0) g_X[w] = p + g_c[sg];
}

// ---- per-segment scaled softmax + weighted max-pool + gate ----------------
__global__ __launch_bounds__(256) void k_pool(const int* __restrict__ csr,
                                              const float* __restrict__ xmod,
                                              float* __restrict__ out,
                                              int N, int hasSeen) {
    int warp = (blockIdx.x * blockDim.x + threadIdx.x) >> 5;
    int lane = threadIdx.x & 31;
    if (warp >= N) return;
    int s = csr[warp], e = csr[warp + 1];
    int cnt = e - s;
    float* orow = out + (size_t)warp * 128;
    if (cnt <= 0) {
        orow[lane] = 0.f; orow[lane + 32] = 0.f;
        orow[lane + 64] = 0.f; orow[lane + 96] = 0.f;
        if (hasSeen && lane == 0) out[(size_t)N * 128 + warp] = 0.f;
        return;
    }
    const float NEG_INF = __int_as_float(0xff800000);
    float m = NEG_INF;
    for (int v = s + lane; v < e; v += 32) m = fmaxf(m, g_X[v]);
#pragma unroll
    for (int o = 16; o; o >>= 1) m = fmaxf(m, __shfl_xor_sync(0xffffffffu, m, o));
    float inv = rsqrtf((float)cnt);
    float ss = 0.f;
    for (int v = s + lane; v < e; v += 32) ss += expf((g_X[v] - m) * inv);
#pragma unroll
    for (int o = 16; o; o >>= 1) ss += __shfl_xor_sync(0xffffffffu, ss, o);
    float denom = ss + 1e-12f;
    float G = tanhf(fmaxf(m, 0.f));
    float p0 = NEG_INF, p1 = NEG_INF, p2 = NEG_INF, p3 = NEG_INF;
    for (int v = s; v < e; ++v) {
        float a = expf((g_X[v] - m) * inv) / denom;
        const float* xr = xmod + (size_t)v * 128;
        p0 = fmaxf(p0, xr[lane] * a);
        p1 = fmaxf(p1, xr[lane + 32] * a);
        p2 = fmaxf(p2, xr[lane + 64] * a);
        p3 = fmaxf(p3, xr[lane + 96] * a);
    }
    orow[lane]      = p0 * G;
    orow[lane + 32] = p1 * G;
    orow[lane + 64] = p2 * G;
    orow[lane + 96] = p3 * G;
    if (hasSeen && lane == 0) out[(size_t)N * 128 + warp] = 1.f;
}

// ---------------------------------------------------------------------------
extern "C" void kernel_launch(void* const* d_in, const int* in_sizes, int n_in,
                              void* d_out, int out_size) {
    const float* x_main = (const float*)d_in[0];
    const float* x_mod  = (const float*)d_in[1];
    const float* x_proj = (const float*)d_in[2];
    const int*   csr    = (const int*)d_in[3];
    const float* Wq = (const float*)d_in[4];
    const float* bq = (const float*)d_in[5];
    const float* W1 = (const float*)d_in[6];
    const float* b1 = (const float*)d_in[7];
    const float* g1 = (const float*)d_in[8];
    const float* be1 = (const float*)d_in[9];
    const float* W2 = (const float*)d_in[10];
    const float* b2 = (const float*)d_in[11];
    const float* g2 = (const float*)d_in[12];
    const float* be2 = (const float*)d_in[13];
    const float* Wk = (const float*)d_in[14];
    const float* bk = (const float*)d_in[15];

    int N = in_sizes[0] / 64;
    int V = in_sizes[1] / 128;
    float* out = (float*)d_out;
    int hasSeen = (out_size >= N * 129) ? 1 : 0;
    float invV = 1.0f / (float)V;

    int vb128 = (V + 127) / 128;
    int nb128 = (N + 127) / 128;

    k_zero_stats<<<1, 256>>>();
    k_seg<<<(N + 255) / 256, 256>>>(csr, N);
    k_prep<<<1, 256>>>(Wq, bq, Wk, bk);
    k_stats1<<<vb128, 128>>>(x_proj, W1, b1, V);
    k_finalize<<<1, 64>>>(g1, be1, 0, invV);
    k_fused12<<<vb128, 128>>>(x_proj, b1, W1, W2, b2, V);
    k_finalize<<<1, 64>>>(g2, be2, 1, invV);
    {
        dim3 g(nb128, 3);
        k_R<<<g, 128>>>(x_main, N);
    }
    k_c<<<(N * 32 + 255) / 256, 256>>>(x_main, N);
    k_score<<<(V * 32 + 255) / 256, 256>>>(x_mod, V);
    k_pool<<<(N * 32 + 255) / 256, 256>>>(csr, x_mod, out, N, hasSeen);
}